// round 1
// baseline (speedup 1.0000x reference)
#include <cuda_runtime.h>
#include <mma.h>
#include <math.h>

using namespace nvcuda;

// Problem constants
#define Bn 4
#define Ln 2048
#define Dn 768
#define Hn 12
#define Kn 9
#define IPGn 64
#define PADn 4

// v scratch: B*L*D fp32 (25.2 MB)
__device__ float g_v[Bn * Ln * Dn];

// ---------------------------------------------------------------------------
// Kernel 1: v = query @ pt_w.T   (M=8192, N=768, K=768), tf32 tensor cores.
// A = query row-major (lda=768). B(k,n) = pt_w[n,k] -> pt_w is col-major B
// with ldb=768. No bias here (folded into fused kernel's v-tile load).
// Block tile 128x64, K-chunk 32, 8 warps (4x2), each warp 32x32 via 2x2
// m16n16k8 fragments.
// ---------------------------------------------------------------------------
#define BM 128
#define BN 64
#define BK 32
#define LDA_S 36
#define LDB_S 36

__global__ __launch_bounds__(256) void gemm_v_kernel(
    const float* __restrict__ A, const float* __restrict__ W)
{
    __shared__ __align__(16) float As[BM * LDA_S];
    __shared__ __align__(16) float Bs[BN * LDB_S];

    const int tid = threadIdx.x;
    const int m0 = blockIdx.y * BM;
    const int n0 = blockIdx.x * BN;
    const int warp = tid >> 5;
    const int wm = warp & 3;   // 0..3 -> 32-row strip
    const int wn = warp >> 2;  // 0..1 -> 32-col strip

    wmma::fragment<wmma::accumulator, 16, 16, 8, float> cf[2][2];
#pragma unroll
    for (int mi = 0; mi < 2; mi++)
#pragma unroll
        for (int ni = 0; ni < 2; ni++)
            wmma::fill_fragment(cf[mi][ni], 0.0f);

    for (int k0 = 0; k0 < Dn; k0 += BK) {
        // Load A tile: 128 x 32 floats = 1024 float4, 4 per thread
#pragma unroll
        for (int v = 0; v < 4; v++) {
            int idx = tid + v * 256;
            int r = idx >> 3;        // row 0..127
            int c4 = idx & 7;        // float4 index 0..7
            const float4 src = *reinterpret_cast<const float4*>(
                &A[(size_t)(m0 + r) * Dn + k0 + c4 * 4]);
            *reinterpret_cast<float4*>(&As[r * LDA_S + c4 * 4]) = src;
        }
        // Load B tile (col-major k x n): 64 n-rows x 32 k = 512 float4, 2/thread
#pragma unroll
        for (int v = 0; v < 2; v++) {
            int idx = tid + v * 256;
            int n = idx >> 3;        // 0..63
            int k4 = idx & 7;
            const float4 src = *reinterpret_cast<const float4*>(
                &W[(size_t)(n0 + n) * Dn + k0 + k4 * 4]);
            *reinterpret_cast<float4*>(&Bs[n * LDB_S + k4 * 4]) = src;
        }
        __syncthreads();

#pragma unroll
        for (int ks = 0; ks < 4; ks++) {
            wmma::fragment<wmma::matrix_a, 16, 16, 8, wmma::precision::tf32,
                           wmma::row_major> af[2];
            wmma::fragment<wmma::matrix_b, 16, 16, 8, wmma::precision::tf32,
                           wmma::col_major> bf[2];
#pragma unroll
            for (int mi = 0; mi < 2; mi++) {
                wmma::load_matrix_sync(
                    af[mi], &As[(wm * 32 + mi * 16) * LDA_S + ks * 8], LDA_S);
#pragma unroll
                for (int t = 0; t < af[mi].num_elements; t++)
                    af[mi].x[t] = wmma::__float_to_tf32(af[mi].x[t]);
            }
#pragma unroll
            for (int ni = 0; ni < 2; ni++) {
                wmma::load_matrix_sync(
                    bf[ni], &Bs[(wn * 32 + ni * 16) * LDB_S + ks * 8], LDB_S);
#pragma unroll
                for (int t = 0; t < bf[ni].num_elements; t++)
                    bf[ni].x[t] = wmma::__float_to_tf32(bf[ni].x[t]);
            }
#pragma unroll
            for (int mi = 0; mi < 2; mi++)
#pragma unroll
                for (int ni = 0; ni < 2; ni++)
                    wmma::mma_sync(cf[mi][ni], af[mi], bf[ni], cf[mi][ni]);
        }
        __syncthreads();
    }

#pragma unroll
    for (int mi = 0; mi < 2; mi++)
#pragma unroll
        for (int ni = 0; ni < 2; ni++)
            wmma::store_matrix_sync(
                &g_v[(size_t)(m0 + wm * 32 + mi * 16) * Dn + n0 + wn * 32 + ni * 16],
                cf[mi][ni], Dn, wmma::mem_row_major);
}

// ---------------------------------------------------------------------------
// Kernel 2: fused depthwise conv -> per-head pointwise -> gate -> attention
// kernel -> softmax -> windowed gather from v.
// Block = (l_tile of 32, head, batch). 256 threads: col = tid&63 (channel in
// head), row4 = tid>>6; each thread handles 8 positions.
// ---------------------------------------------------------------------------
#define LT 32
#define RT (LT + 2 * PADn)  // 40 rows incl. halo

__global__ __launch_bounds__(256) void sdconv_fused(
    const float* __restrict__ q,
    const float* __restrict__ dw_w,
    const float* __restrict__ pw_w,
    const float* __restrict__ pw_b,
    const float* __restrict__ ak_w,
    const float* __restrict__ ak_b,
    const float* __restrict__ pt_b,
    float* __restrict__ out)
{
    __shared__ float qs[RT * 64];      // query tile, later reused as v tile
    __shared__ float dws[LT * 64];     // depthwise out, later conv_attn
    __shared__ float pwwT[64 * 65];    // pw_w[h] transposed [i][o], padded
    __shared__ float dwws[64 * 9];     // dw_w[h] as [i][k]
    __shared__ float akws[9 * 64];     // ak_w[h] as [k][i]
    __shared__ float wsm[LT * 12];     // kern / softmax weights
    __shared__ float pwbs[64], ptbs[64], akbs[9];

    const int tid = threadIdx.x;
    const int bb = blockIdx.z;
    const int h = blockIdx.y;
    const int l0 = blockIdx.x * LT;
    const int hbase = h * IPGn;

    // -------- load query tile (with zero halo) + per-head weights --------
    for (int idx = tid; idx < RT * 64; idx += 256) {
        int r = idx >> 6, i = idx & 63;
        int gl = l0 - PADn + r;
        qs[idx] = (gl >= 0 && gl < Ln)
                      ? q[((size_t)(bb * Ln + gl)) * Dn + hbase + i] : 0.0f;
    }
    for (int idx = tid; idx < 64 * 64; idx += 256) {
        int o = idx >> 6, i = idx & 63;
        pwwT[i * 65 + o] = pw_w[h * 4096 + idx];   // pw_w[h][o][i]
    }
    for (int idx = tid; idx < 64 * 9; idx += 256)
        dwws[idx] = dw_w[hbase * 9 + idx];          // (hbase+i)*9+k
    for (int idx = tid; idx < 9 * 64; idx += 256)
        akws[idx] = ak_w[h * 9 * 64 + idx];         // ak_w[h][k][i]
    if (tid < 64) { pwbs[tid] = pw_b[hbase + tid]; ptbs[tid] = pt_b[hbase + tid]; }
    if (tid < 9)  akbs[tid] = ak_b[h * 9 + tid];
    __syncthreads();

    const int col = tid & 63;
    const int row4 = tid >> 6;

    // -------- depthwise conv: dws[l][col] --------
    float wk[9];
#pragma unroll
    for (int k = 0; k < 9; k++) wk[k] = dwws[col * 9 + k];
#pragma unroll
    for (int j = 0; j < 8; j++) {
        int l = row4 * 8 + j;
        float s = 0.0f;
#pragma unroll
        for (int k = 0; k < 9; k++) s += qs[(l + k) * 64 + col] * wk[k];
        dws[l * 64 + col] = s;
    }
    __syncthreads();

    // -------- pointwise (64x64 per head) + bias, then gate by query --------
    float acc[8];
#pragma unroll
    for (int j = 0; j < 8; j++) acc[j] = pwbs[col];
    for (int i = 0; i < 64; i++) {
        float wv = pwwT[i * 65 + col];
#pragma unroll
        for (int j = 0; j < 8; j++)
            acc[j] += dws[(row4 * 8 + j) * 64 + i] * wv;   // broadcast read
    }
#pragma unroll
    for (int j = 0; j < 8; j++)
        acc[j] *= qs[(row4 * 8 + j + PADn) * 64 + col];    // conv_attn
    __syncthreads();
#pragma unroll
    for (int j = 0; j < 8; j++)
        dws[(row4 * 8 + j) * 64 + col] = acc[j];           // dws now = ca
    __syncthreads();

    // -------- load v tile into qs (reuse) with bias fold + zero halo --------
    for (int idx = tid; idx < RT * 64; idx += 256) {
        int r = idx >> 6, i = idx & 63;
        int gl = l0 - PADn + r;
        qs[idx] = (gl >= 0 && gl < Ln)
                      ? g_v[((size_t)(bb * Ln + gl)) * Dn + hbase + i] + ptbs[i]
                      : 0.0f;
    }

    // -------- attention kernel: wsm[l][k] = ca[l] . ak_w[h][k] + b --------
    for (int t = tid; t < LT * 9; t += 256) {
        int l = t / 9, k = t - l * 9;
        float s = akbs[k];
        for (int i = 0; i < 64; i++)
            s += dws[l * 64 + i] * akws[k * 64 + i];
        wsm[l * 12 + k] = s;
    }
    __syncthreads();

    // -------- softmax over k (one thread per position) --------
    if (tid < LT) {
        int l = tid;
        float m = -1e30f;
#pragma unroll
        for (int k = 0; k < 9; k++) m = fmaxf(m, wsm[l * 12 + k]);
        float e[9], sm = 0.0f;
#pragma unroll
        for (int k = 0; k < 9; k++) { e[k] = expf(wsm[l * 12 + k] - m); sm += e[k]; }
        float inv = 1.0f / sm;
#pragma unroll
        for (int k = 0; k < 9; k++) wsm[l * 12 + k] = e[k] * inv;
    }
    __syncthreads();

    // -------- windowed gather: out[l][col] = sum_k v[l+k-4][col] * w[l][k] --
#pragma unroll
    for (int j = 0; j < 8; j++) {
        int l = row4 * 8 + j;
        float s = 0.0f;
#pragma unroll
        for (int k = 0; k < 9; k++)
            s += qs[(l + k) * 64 + col] * wsm[l * 12 + k];
        out[((size_t)(bb * Ln + l0 + l)) * Dn + hbase + col] = s;
    }
}

// ---------------------------------------------------------------------------
extern "C" void kernel_launch(void* const* d_in, const int* in_sizes, int n_in,
                              void* d_out, int out_size)
{
    const float* query = (const float*)d_in[0];
    const float* dw_w  = (const float*)d_in[1];
    const float* pw_w  = (const float*)d_in[2];
    const float* pw_b  = (const float*)d_in[3];
    const float* ak_w  = (const float*)d_in[4];
    const float* ak_b  = (const float*)d_in[5];
    const float* pt_w  = (const float*)d_in[6];
    const float* pt_b  = (const float*)d_in[7];
    float* out = (float*)d_out;

    dim3 ggrid(Dn / BN, (Bn * Ln) / BM);       // 12 x 64
    gemm_v_kernel<<<ggrid, 256>>>(query, pt_w);

    dim3 fgrid(Ln / LT, Hn, Bn);               // 64 x 12 x 4
    sdconv_fused<<<fgrid, 256>>>(query, dw_w, pw_w, pw_b, ak_w, ak_b, pt_b, out);
}

// round 2
// speedup vs baseline: 1.2924x; 1.2924x over previous
#include <cuda_runtime.h>
#include <mma.h>
#include <math.h>

using namespace nvcuda;

#define Bn 4
#define Ln 2048
#define Dn 768
#define Hn 12
#define Kn 9
#define IPGn 64
#define PADn 4

__device__ float g_v[Bn * Ln * Dn];

// ---------------------------------------------------------------------------
// cp.async helpers
// ---------------------------------------------------------------------------
__device__ __forceinline__ void cp_async16(void* smem, const void* gmem) {
    unsigned s = (unsigned)__cvta_generic_to_shared(smem);
    asm volatile("cp.async.cg.shared.global [%0], [%1], 16;\n" :: "r"(s), "l"(gmem));
}
__device__ __forceinline__ void cp_commit() {
    asm volatile("cp.async.commit_group;\n" ::);
}
template <int N>
__device__ __forceinline__ void cp_wait() {
    asm volatile("cp.async.wait_group %0;\n" :: "n"(N));
}

// ---------------------------------------------------------------------------
// Kernel 1: v = query @ pt_w.T  (M=8192, N=768, K=768) tf32 tensor cores.
// 128x128 block tile, BK=16 double-buffered cp.async, 8 warps (2m x 4n),
// each warp 64x32 via 4x2 m16n16k8 fragments.
// ---------------------------------------------------------------------------
#define GBM 128
#define GBN 128
#define GBK 16
#define GLD 20  // padded row stride (floats); 80B rows keep 16B alignment

__device__ __forceinline__ void gemm_load_tile(
    const float* __restrict__ A, const float* __restrict__ W,
    float* As, float* Bs, int m0, int n0, int k0, int tid)
{
#pragma unroll
    for (int v = 0; v < 2; v++) {
        int idx = tid + v * 256;
        int r = idx >> 2, c4 = idx & 3;
        cp_async16(&As[r * GLD + c4 * 4], &A[(size_t)(m0 + r) * Dn + k0 + c4 * 4]);
    }
#pragma unroll
    for (int v = 0; v < 2; v++) {
        int idx = tid + v * 256;
        int r = idx >> 2, c4 = idx & 3;
        cp_async16(&Bs[r * GLD + c4 * 4], &W[(size_t)(n0 + r) * Dn + k0 + c4 * 4]);
    }
}

__global__ __launch_bounds__(256) void gemm_v2(
    const float* __restrict__ A, const float* __restrict__ W)
{
    __shared__ __align__(16) float As[2][GBM * GLD];
    __shared__ __align__(16) float Bs[2][GBN * GLD];

    const int tid = threadIdx.x;
    const int m0 = blockIdx.y * GBM;
    const int n0 = blockIdx.x * GBN;
    const int warp = tid >> 5;
    const int wm = warp & 1;    // 0..1 -> 64-row strip
    const int wn = warp >> 1;   // 0..3 -> 32-col strip

    wmma::fragment<wmma::accumulator, 16, 16, 8, float> cf[4][2];
#pragma unroll
    for (int mi = 0; mi < 4; mi++)
#pragma unroll
        for (int ni = 0; ni < 2; ni++)
            wmma::fill_fragment(cf[mi][ni], 0.0f);

    gemm_load_tile(A, W, As[0], Bs[0], m0, n0, 0, tid);
    cp_commit();

    const int NKT = Dn / GBK;  // 48
    for (int kt = 0; kt < NKT; kt++) {
        const int cur = kt & 1;
        if (kt + 1 < NKT) {
            gemm_load_tile(A, W, As[cur ^ 1], Bs[cur ^ 1], m0, n0, (kt + 1) * GBK, tid);
            cp_commit();
            cp_wait<1>();
        } else {
            cp_wait<0>();
        }
        __syncthreads();

#pragma unroll
        for (int ks = 0; ks < GBK / 8; ks++) {
            wmma::fragment<wmma::matrix_a, 16, 16, 8, wmma::precision::tf32,
                           wmma::row_major> af[4];
            wmma::fragment<wmma::matrix_b, 16, 16, 8, wmma::precision::tf32,
                           wmma::col_major> bf[2];
#pragma unroll
            for (int mi = 0; mi < 4; mi++) {
                wmma::load_matrix_sync(
                    af[mi], &As[cur][(wm * 64 + mi * 16) * GLD + ks * 8], GLD);
#pragma unroll
                for (int t = 0; t < af[mi].num_elements; t++)
                    af[mi].x[t] = wmma::__float_to_tf32(af[mi].x[t]);
            }
#pragma unroll
            for (int ni = 0; ni < 2; ni++) {
                wmma::load_matrix_sync(
                    bf[ni], &Bs[cur][(wn * 32 + ni * 16) * GLD + ks * 8], GLD);
#pragma unroll
                for (int t = 0; t < bf[ni].num_elements; t++)
                    bf[ni].x[t] = wmma::__float_to_tf32(bf[ni].x[t]);
            }
#pragma unroll
            for (int mi = 0; mi < 4; mi++)
#pragma unroll
                for (int ni = 0; ni < 2; ni++)
                    wmma::mma_sync(cf[mi][ni], af[mi], bf[ni], cf[mi][ni]);
        }
        __syncthreads();
    }

#pragma unroll
    for (int mi = 0; mi < 4; mi++)
#pragma unroll
        for (int ni = 0; ni < 2; ni++)
            wmma::store_matrix_sync(
                &g_v[(size_t)(m0 + wm * 64 + mi * 16) * Dn + n0 + wn * 32 + ni * 16],
                cf[mi][ni], Dn, wmma::mem_row_major);
}

// ---------------------------------------------------------------------------
// Kernel 2: fused depthwise conv -> pointwise -> gate -> attn kernel ->
// softmax -> windowed gather. LT=64 positions/block, 512 threads.
// Padded smem strides (65) remove the stride-64 bank conflicts that made
// the R1 version L1-bound.
// ---------------------------------------------------------------------------
#define LT 64
#define RT (LT + 2 * PADn)  // 72 rows incl. halo

// dynamic smem layout (floats):
#define OFF_QS    0                      // RT*64   = 4608
#define OFF_DWS   (OFF_QS + RT * 64)     // 64*65   = 4160
#define OFF_PWWT  (OFF_DWS + 64 * 65)    // 64*65   = 4160
#define OFF_DWWS  (OFF_PWWT + 64 * 65)   // 64*9    = 576
#define OFF_AKWS  (OFF_DWWS + 64 * 9)    // 9*65    = 585
#define OFF_WSM   (OFF_AKWS + 9 * 65)    // 64*12   = 768
#define OFF_PWB   (OFF_WSM + LT * 12)    // 64
#define OFF_PTB   (OFF_PWB + 64)         // 64
#define OFF_AKB   (OFF_PTB + 64)         // 16
#define SMEM_FLOATS (OFF_AKB + 16)
#define SMEM_BYTES (SMEM_FLOATS * 4)

__global__ __launch_bounds__(512) void sdconv_fused(
    const float* __restrict__ q,
    const float* __restrict__ dw_w,
    const float* __restrict__ pw_w,
    const float* __restrict__ pw_b,
    const float* __restrict__ ak_w,
    const float* __restrict__ ak_b,
    const float* __restrict__ pt_b,
    float* __restrict__ out)
{
    extern __shared__ float sm[];
    float* qs   = sm + OFF_QS;    // query tile, later reused as v tile
    float* dws  = sm + OFF_DWS;   // depthwise out, later conv_attn (stride 65)
    float* pwwT = sm + OFF_PWWT;  // pw_w[h] transposed [i][o] (stride 65)
    float* dwws = sm + OFF_DWWS;  // dw_w[h] as [i][k]
    float* akws = sm + OFF_AKWS;  // ak_w[h] as [k][i] (stride 65)
    float* wsm  = sm + OFF_WSM;   // kern / softmax weights (stride 12)
    float* pwbs = sm + OFF_PWB;
    float* ptbs = sm + OFF_PTB;
    float* akbs = sm + OFF_AKB;

    const int tid = threadIdx.x;
    const int bb = blockIdx.z;
    const int h = blockIdx.y;
    const int l0 = blockIdx.x * LT;
    const int hbase = h * IPGn;

    // -------- load query tile (zero halo) + per-head weights --------
    for (int idx = tid; idx < RT * 64; idx += 512) {
        int r = idx >> 6, i = idx & 63;
        int gl = l0 - PADn + r;
        qs[idx] = (gl >= 0 && gl < Ln)
                      ? q[((size_t)(bb * Ln + gl)) * Dn + hbase + i] : 0.0f;
    }
    for (int idx = tid; idx < 64 * 64; idx += 512) {
        int o = idx >> 6, i = idx & 63;
        pwwT[i * 65 + o] = pw_w[h * 4096 + idx];   // pw_w[h][o][i]
    }
    for (int idx = tid; idx < 64 * 9; idx += 512)
        dwws[idx] = dw_w[hbase * 9 + idx];
    for (int idx = tid; idx < 9 * 64; idx += 512) {
        int k = idx >> 6, i = idx & 63;
        akws[k * 65 + i] = ak_w[h * 9 * 64 + idx];
    }
    if (tid < 64) { pwbs[tid] = pw_b[hbase + tid]; ptbs[tid] = pt_b[hbase + tid]; }
    if (tid < 9)  akbs[tid] = ak_b[h * 9 + tid];
    __syncthreads();

    const int col = tid & 63;
    const int row8 = tid >> 6;   // 0..7, each handles 8 positions

    // -------- depthwise conv: dws[l][col] --------
    float wk[9];
#pragma unroll
    for (int k = 0; k < 9; k++) wk[k] = dwws[col * 9 + k];
#pragma unroll
    for (int j = 0; j < 8; j++) {
        int l = row8 * 8 + j;
        float s = 0.0f;
#pragma unroll
        for (int k = 0; k < 9; k++) s += qs[(l + k) * 64 + col] * wk[k];
        dws[l * 65 + col] = s;
    }
    __syncthreads();

    // -------- pointwise (64x64) + bias, gate by query --------
    float acc[8];
#pragma unroll
    for (int j = 0; j < 8; j++) acc[j] = pwbs[col];
    for (int i = 0; i < 64; i++) {
        float wv = pwwT[i * 65 + col];
#pragma unroll
        for (int j = 0; j < 8; j++)
            acc[j] += dws[(row8 * 8 + j) * 65 + i] * wv;  // broadcast read
    }
#pragma unroll
    for (int j = 0; j < 8; j++)
        acc[j] *= qs[(row8 * 8 + j + PADn) * 64 + col];   // conv_attn
    __syncthreads();
#pragma unroll
    for (int j = 0; j < 8; j++)
        dws[(row8 * 8 + j) * 65 + col] = acc[j];          // dws now = ca
    __syncthreads();

    // -------- load v tile into qs (reuse) with bias fold + zero halo --------
    for (int idx = tid; idx < RT * 64; idx += 512) {
        int r = idx >> 6, i = idx & 63;
        int gl = l0 - PADn + r;
        qs[idx] = (gl >= 0 && gl < Ln)
                      ? g_v[((size_t)(bb * Ln + gl)) * Dn + hbase + i] + ptbs[i]
                      : 0.0f;
    }

    // -------- attention kernel: wsm[l][k] = ca[l] . ak_w[h][k] + b --------
    for (int t = tid; t < LT * 9; t += 512) {
        int l = t / 9, k = t - l * 9;
        float s = akbs[k];
        for (int i = 0; i < 64; i++)
            s += dws[l * 65 + i] * akws[k * 65 + i];
        wsm[l * 12 + k] = s;
    }
    __syncthreads();

    // -------- softmax over k --------
    if (tid < LT) {
        int l = tid;
        float m = -1e30f;
#pragma unroll
        for (int k = 0; k < 9; k++) m = fmaxf(m, wsm[l * 12 + k]);
        float e[9], smx = 0.0f;
#pragma unroll
        for (int k = 0; k < 9; k++) { e[k] = expf(wsm[l * 12 + k] - m); smx += e[k]; }
        float inv = 1.0f / smx;
#pragma unroll
        for (int k = 0; k < 9; k++) wsm[l * 12 + k] = e[k] * inv;
    }
    __syncthreads();

    // -------- windowed gather --------
#pragma unroll
    for (int j = 0; j < 8; j++) {
        int l = row8 * 8 + j;
        float s = 0.0f;
#pragma unroll
        for (int k = 0; k < 9; k++)
            s += qs[(l + k) * 64 + col] * wsm[l * 12 + k];
        out[((size_t)(bb * Ln + l0 + l)) * Dn + hbase + col] = s;
    }
}

// ---------------------------------------------------------------------------
extern "C" void kernel_launch(void* const* d_in, const int* in_sizes, int n_in,
                              void* d_out, int out_size)
{
    const float* query = (const float*)d_in[0];
    const float* dw_w  = (const float*)d_in[1];
    const float* pw_w  = (const float*)d_in[2];
    const float* pw_b  = (const float*)d_in[3];
    const float* ak_w  = (const float*)d_in[4];
    const float* ak_b  = (const float*)d_in[5];
    const float* pt_w  = (const float*)d_in[6];
    const float* pt_b  = (const float*)d_in[7];
    float* out = (float*)d_out;

    cudaFuncSetAttribute(sdconv_fused,
                         cudaFuncAttributeMaxDynamicSharedMemorySize, SMEM_BYTES);

    dim3 ggrid(Dn / GBN, (Bn * Ln) / GBM);     // 6 x 64
    gemm_v2<<<ggrid, 256>>>(query, pt_w);

    dim3 fgrid(Ln / LT, Hn, Bn);               // 32 x 12 x 4
    sdconv_fused<<<fgrid, 512, SMEM_BYTES>>>(query, dw_w, pw_w, pw_b,
                                             ak_w, ak_b, pt_b, out);
}